// round 1
// baseline (speedup 1.0000x reference)
#include <cuda_runtime.h>
#include <cstddef>

#define B_ 64
#define Q_ 256
#define D_ 768
#define THRESH 0.9f
#define EPSN 1e-12f

#define QW (Q_/32)            // 8 words of flag bits per row

__device__ float    g_norm[B_*Q_];
__device__ unsigned g_flag[Q_*QW];   // bit (i*Q+j): pair flagged (only j>i ever set)
__device__ int      g_any;

// ---------------------------------------------------------------------------
// Kernel 1: row L2 norms (clamped to eps) + zero flag state.
// warp per row; 2048 blocks x 256 threads.
// ---------------------------------------------------------------------------
__global__ void k_norm(const float* __restrict__ c) {
    int row  = blockIdx.x * 8 + (threadIdx.x >> 5);
    int lane = threadIdx.x & 31;
    if (blockIdx.x == 0) {
        for (int w = threadIdx.x; w < Q_*QW; w += 256) g_flag[w] = 0u;
        if (threadIdx.x == 0) g_any = 0;
    }
    const float4* p = (const float4*)(c + (size_t)row * D_);
    float s = 0.f;
    #pragma unroll
    for (int i = 0; i < 6; i++) {
        float4 v = p[lane + 32*i];
        s += v.x*v.x + v.y*v.y + v.z*v.z + v.w*v.w;
    }
    #pragma unroll
    for (int o = 16; o; o >>= 1) s += __shfl_xor_sync(0xFFFFFFFFu, s, o);
    if (lane == 0) g_norm[row] = fmaxf(sqrtf(s), EPSN);
}

// ---------------------------------------------------------------------------
// Kernel 2: upper-triangular tile Gram; flag pairs with dot > 0.9*ni*nj.
// BM=BN=64, BK=16, 256 threads, 4x4 micro-tile. grid = (10 tile-pairs, 64 batches)
// ---------------------------------------------------------------------------
#define BM 64
#define BN 64
#define BK 16
#define PAD 4   // smem row stride 68 (multiple of 4 for float4 reads)

__global__ void k_sim(const float* __restrict__ c) {
    int p = blockIdx.x;
    int ti, tj;
    if      (p < 4) { ti = 0; tj = p;     }
    else if (p < 7) { ti = 1; tj = p - 3; }
    else if (p < 9) { ti = 2; tj = p - 5; }
    else            { ti = 3; tj = 3;     }
    int b = blockIdx.y;
    const float* Cb = c + (size_t)b * Q_ * D_;

    __shared__ __align__(16) float As[BK][BM+PAD];
    __shared__ __align__(16) float Bs[BK][BN+PAD];

    int tid = threadIdx.x;            // 0..255
    int lr  = tid >> 2;               // 0..63  load row
    int lk  = (tid & 3) << 2;         // 0,4,8,12 load k offset
    int ty  = tid >> 4;               // 0..15
    int tx  = tid & 15;               // 0..15

    float acc[4][4];
    #pragma unroll
    for (int u = 0; u < 4; u++)
        #pragma unroll
        for (int v = 0; v < 4; v++) acc[u][v] = 0.f;

    const float* aRow = Cb + (size_t)(ti*BM + lr) * D_ + lk;
    const float* bRow = Cb + (size_t)(tj*BN + lr) * D_ + lk;

    for (int k0 = 0; k0 < D_; k0 += BK) {
        float4 av = *(const float4*)(aRow + k0);
        float4 bv = *(const float4*)(bRow + k0);
        As[lk+0][lr] = av.x; As[lk+1][lr] = av.y;
        As[lk+2][lr] = av.z; As[lk+3][lr] = av.w;
        Bs[lk+0][lr] = bv.x; Bs[lk+1][lr] = bv.y;
        Bs[lk+2][lr] = bv.z; Bs[lk+3][lr] = bv.w;
        __syncthreads();
        #pragma unroll
        for (int k = 0; k < BK; k++) {
            float4 a4 = *(const float4*)&As[k][ty*4];
            float4 b4 = *(const float4*)&Bs[k][tx*4];
            float ar[4] = {a4.x, a4.y, a4.z, a4.w};
            float br[4] = {b4.x, b4.y, b4.z, b4.w};
            #pragma unroll
            for (int u = 0; u < 4; u++)
                #pragma unroll
                for (int v = 0; v < 4; v++)
                    acc[u][v] = fmaf(ar[u], br[v], acc[u][v]);
        }
        __syncthreads();
    }

    #pragma unroll
    for (int u = 0; u < 4; u++) {
        int i = ti*BM + ty*4 + u;
        float ni = g_norm[b*Q_ + i];
        #pragma unroll
        for (int v = 0; v < 4; v++) {
            int j = tj*BN + tx*4 + v;
            if (j > i) {
                float nj = g_norm[b*Q_ + j];
                if (acc[u][v] > THRESH * ni * nj) {
                    atomicOr(&g_flag[i*QW + (j >> 5)], 1u << (j & 31));
                    g_any = 1;
                }
            }
        }
    }
}

// ---------------------------------------------------------------------------
// Kernel 3: copy input -> output (float4)
// ---------------------------------------------------------------------------
__global__ void k_copy(const float4* __restrict__ in, float4* __restrict__ out, int n4) {
    int i = blockIdx.x * blockDim.x + threadIdx.x;
    if (i < n4) out[i] = in[i];
}

// ---------------------------------------------------------------------------
// Kernel 4: sequential merge (single block). Fast exit when no flags (common).
// Processes flagged pairs in row-major upper-tri order; merges are in-place
// on the output buffer; __syncthreads orders successive merges.
// ---------------------------------------------------------------------------
__global__ void k_merge(float* __restrict__ out) {
    if (g_any == 0) return;
    __shared__ unsigned fl[Q_*QW];
    for (int w = threadIdx.x; w < Q_*QW; w += blockDim.x) fl[w] = g_flag[w];
    __syncthreads();
    for (int i = 0; i < Q_ - 1; i++) {
        for (int w = 0; w < QW; w++) {
            unsigned m = fl[i*QW + w];          // uniform across threads
            while (m) {
                int j = w*32 + __ffs(m) - 1;
                m &= m - 1;
                for (int t = threadIdx.x; t < B_*D_; t += blockDim.x) {
                    int b = t / D_, d = t % D_;
                    size_t oi = (size_t)b*Q_*D_ + (size_t)i*D_ + d;
                    size_t oj = (size_t)b*Q_*D_ + (size_t)j*D_ + d;
                    float nv = 0.5f * (out[oi] + out[oj]);
                    out[oi] = nv;
                    out[oj] = nv;
                }
                __syncthreads();
            }
        }
    }
}

// ---------------------------------------------------------------------------
extern "C" void kernel_launch(void* const* d_in, const int* in_sizes, int n_in,
                              void* d_out, int out_size) {
    (void)in_sizes; (void)n_in; (void)out_size;
    const float* c = (const float*)d_in[0];
    float* out = (float*)d_out;

    k_norm<<<(B_*Q_)/8, 256>>>(c);

    dim3 g(10, B_);
    k_sim<<<g, 256>>>(c);

    int n4 = B_*Q_*D_/4;
    k_copy<<<(n4 + 255)/256, 256>>>((const float4*)c, (float4*)out, n4);

    k_merge<<<1, 1024>>>(out);
}

// round 2
// speedup vs baseline: 2.5869x; 2.5869x over previous
#include <cuda_runtime.h>
#include <cuda_bf16.h>
#include <cstdint>
#include <cstddef>

#define B_ 64
#define Q_ 256
#define D_ 768
#define THRESH 0.9f
#define MARGIN 0.02f          // >> bf16 screen error bound (~0.004*ni*nj)
#define EPSN 1e-12f
#define QW (Q_/32)

__device__ float    g_norm[B_*Q_];
__device__ unsigned g_flag[Q_*QW];
__device__ int      g_any;
__device__ int      g_ncand;
#define CAND_MAX (B_*(Q_*(Q_-1)/2))   // theoretical max candidates: cannot overflow
__device__ int2     g_cand[CAND_MAX];
__device__ __nv_bfloat16 g_bf[(size_t)B_*Q_*D_];

// ---------------------------------------------------------------------------
// Kernel 1: fused  (a) row L2 norms  (b) copy input->output  (c) fp32->bf16
// warp per row; 2048 blocks x 256 threads. Block 0 zeroes flag state.
// ---------------------------------------------------------------------------
__global__ void k_prep(const float* __restrict__ in, float* __restrict__ out) {
    int row  = blockIdx.x * 8 + (threadIdx.x >> 5);
    int lane = threadIdx.x & 31;
    if (blockIdx.x == 0) {
        for (int w = threadIdx.x; w < Q_*QW; w += 256) g_flag[w] = 0u;
        if (threadIdx.x == 0) { g_any = 0; g_ncand = 0; }
    }
    const float4* p = (const float4*)(in + (size_t)row * D_);
    float4*       o = (float4*)(out + (size_t)row * D_);
    uint2*       bp = (uint2*)(g_bf + (size_t)row * D_);
    float s = 0.f;
    #pragma unroll
    for (int i = 0; i < 6; i++) {
        float4 v = p[lane + 32*i];
        o[lane + 32*i] = v;
        __nv_bfloat162 lo = __floats2bfloat162_rn(v.x, v.y);
        __nv_bfloat162 hi = __floats2bfloat162_rn(v.z, v.w);
        uint2 u;
        u.x = *(unsigned*)&lo;
        u.y = *(unsigned*)&hi;
        bp[lane + 32*i] = u;
        s += v.x*v.x + v.y*v.y + v.z*v.z + v.w*v.w;
    }
    #pragma unroll
    for (int off = 16; off; off >>= 1) s += __shfl_xor_sync(0xFFFFFFFFu, s, off);
    if (lane == 0) g_norm[row] = fmaxf(sqrtf(s), EPSN);
}

// ---------------------------------------------------------------------------
// Kernel 2: bf16 tensor-core Gram screen. 64x64 tiles, upper triangle only.
// 8 warps, warp tile 16x32 via mma.sync.m16n8k16 bf16 -> fp32 acc.
// Survivors of the conservative screen go to the candidate list.
// ---------------------------------------------------------------------------
#define SROW 20   // smem row stride in 32-bit words (32 bf16 data + 8 bf16 pad)

__global__ void __launch_bounds__(256) k_sim() {
    int p = blockIdx.x;  // 0..9 upper-tri tile pairs
    int ti, tj;
    if      (p < 4) { ti = 0; tj = p;     }
    else if (p < 7) { ti = 1; tj = p - 3; }
    else if (p < 9) { ti = 2; tj = p - 5; }
    else            { ti = 3; tj = 3;     }
    int b = blockIdx.y;
    const __nv_bfloat16* base = g_bf + (size_t)b * Q_ * D_;

    __shared__ uint32_t As[64 * SROW];
    __shared__ uint32_t Bs[64 * SROW];

    int tid  = threadIdx.x;
    int lr   = tid >> 2;        // load row 0..63
    int lq   = tid & 3;         // load quad (8 bf16 each)
    int warp = tid >> 5;
    int lane = tid & 31;
    int m0 = (warp >> 1) * 16;  // warp m base within tile
    int n0 = (warp & 1) * 32;   // warp n base within tile

    float acc[4][4];
    #pragma unroll
    for (int nt = 0; nt < 4; nt++)
        #pragma unroll
        for (int c = 0; c < 4; c++) acc[nt][c] = 0.f;

    const __nv_bfloat16* aRow = base + (size_t)(ti*64 + lr) * D_ + lq*8;
    const __nv_bfloat16* bRow = base + (size_t)(tj*64 + lr) * D_ + lq*8;

    for (int k0 = 0; k0 < D_; k0 += 32) {
        uint4 av = *(const uint4*)(aRow + k0);
        uint4 bv = *(const uint4*)(bRow + k0);
        __syncthreads();
        ((uint4*)As)[lr*5 + lq] = av;     // 5 uint4 per row == SROW words
        ((uint4*)Bs)[lr*5 + lq] = bv;
        __syncthreads();
        #pragma unroll
        for (int kk = 0; kk < 32; kk += 16) {
            int aw = (m0 + (lane >> 2)) * SROW + (kk >> 1) + (lane & 3);
            uint32_t a0 = As[aw], a1 = As[aw + 8*SROW];
            uint32_t a2 = As[aw + 4], a3 = As[aw + 8*SROW + 4];
            #pragma unroll
            for (int nt = 0; nt < 4; nt++) {
                int bw = (n0 + nt*8 + (lane >> 2)) * SROW + (kk >> 1) + (lane & 3);
                uint32_t b0 = Bs[bw], b1 = Bs[bw + 4];
                asm volatile(
                    "mma.sync.aligned.m16n8k16.row.col.f32.bf16.bf16.f32 "
                    "{%0,%1,%2,%3}, {%4,%5,%6,%7}, {%8,%9}, {%0,%1,%2,%3};\n"
                    : "+f"(acc[nt][0]), "+f"(acc[nt][1]),
                      "+f"(acc[nt][2]), "+f"(acc[nt][3])
                    : "r"(a0), "r"(a1), "r"(a2), "r"(a3), "r"(b0), "r"(b1));
            }
        }
    }

    const float* nrm = g_norm + b * Q_;
    #pragma unroll
    for (int nt = 0; nt < 4; nt++) {
        #pragma unroll
        for (int c = 0; c < 4; c++) {
            int i = ti*64 + m0 + (lane >> 2) + ((c >= 2) ? 8 : 0);
            int j = tj*64 + n0 + nt*8 + (lane & 3)*2 + (c & 1);
            if (j > i) {
                float lim = (THRESH - MARGIN) * nrm[i] * nrm[j];
                if (acc[nt][c] > lim) {
                    int idx = atomicAdd(&g_ncand, 1);
                    if (idx < CAND_MAX) g_cand[idx] = make_int2(b, i*Q_ + j);
                }
            }
        }
    }
}

// ---------------------------------------------------------------------------
// Kernel 3: exact fp32 recheck of candidates (warp per candidate).
// ---------------------------------------------------------------------------
__global__ void k_recheck(const float* __restrict__ in) {
    int n = g_ncand;
    if (n > CAND_MAX) n = CAND_MAX;
    int warp = blockIdx.x * (blockDim.x >> 5) + (threadIdx.x >> 5);
    int lane = threadIdx.x & 31;
    int nw   = gridDim.x * (blockDim.x >> 5);
    for (int c = warp; c < n; c += nw) {
        int2 cd = g_cand[c];
        int b = cd.x, i = cd.y >> 8, j = cd.y & 255;
        const float4* pi = (const float4*)(in + ((size_t)b*Q_ + i) * D_);
        const float4* pj = (const float4*)(in + ((size_t)b*Q_ + j) * D_);
        float s = 0.f;
        #pragma unroll
        for (int t = 0; t < 6; t++) {
            float4 x = pi[lane + 32*t], y = pj[lane + 32*t];
            s += x.x*y.x + x.y*y.y + x.z*y.z + x.w*y.w;
        }
        #pragma unroll
        for (int off = 16; off; off >>= 1) s += __shfl_xor_sync(0xFFFFFFFFu, s, off);
        if (lane == 0) {
            float ni = g_norm[b*Q_ + i], nj = g_norm[b*Q_ + j];
            if (s > THRESH * ni * nj) {
                atomicOr(&g_flag[i*QW + (j >> 5)], 1u << (j & 31));
                g_any = 1;
            }
        }
    }
}

// ---------------------------------------------------------------------------
// Kernel 4: sequential merge (single block). Fast exit when no flags.
// ---------------------------------------------------------------------------
__global__ void k_merge(float* __restrict__ out) {
    if (g_any == 0) return;
    __shared__ unsigned fl[Q_*QW];
    for (int w = threadIdx.x; w < Q_*QW; w += blockDim.x) fl[w] = g_flag[w];
    __syncthreads();
    for (int i = 0; i < Q_ - 1; i++) {
        for (int w = 0; w < QW; w++) {
            unsigned m = fl[i*QW + w];
            while (m) {
                int j = w*32 + __ffs(m) - 1;
                m &= m - 1;
                for (int t = threadIdx.x; t < B_*D_; t += blockDim.x) {
                    int b = t / D_, d = t % D_;
                    size_t oi = (size_t)b*Q_*D_ + (size_t)i*D_ + d;
                    size_t oj = (size_t)b*Q_*D_ + (size_t)j*D_ + d;
                    float nv = 0.5f * (out[oi] + out[oj]);
                    out[oi] = nv;
                    out[oj] = nv;
                }
                __syncthreads();
            }
        }
    }
}

// ---------------------------------------------------------------------------
extern "C" void kernel_launch(void* const* d_in, const int* in_sizes, int n_in,
                              void* d_out, int out_size) {
    (void)in_sizes; (void)n_in; (void)out_size;
    const float* c = (const float*)d_in[0];
    float* out = (float*)d_out;

    k_prep<<<(B_*Q_)/8, 256>>>(c, out);

    dim3 g(10, B_);
    k_sim<<<g, 256>>>();

    k_recheck<<<64, 256>>>(c);

    k_merge<<<1, 1024>>>(out);
}